// round 14
// baseline (speedup 1.0000x reference)
#include <cuda_runtime.h>
#include <cstdint>

#define Tn 192
#define Hn 1024
#define NHn 16
#define HDn 64
#define H3n 3072

#define SK_QKV 2
#define SK_OUT 4

#define GKS 36   // smem row stride (words) for GEMM tiles (BK=32 wide)
#define AKS 68   // smem row stride (words) for attention Q/K tiles (64 wide)
#define VS  196  // smem row stride for transposed V (192 keys wide)
#define PP  196  // smem row stride for score/P matrix
// Q + (K / Vt overlaid) + P  — K and Vt share one region (never live together)
#define ATTN_SMEM_BYTES ((32*AKS + 192*AKS + 32*PP) * 4)

// Scratch (device globals — no allocation allowed)
__device__ __align__(16) float g_o[Tn * Hn];
__device__ __align__(16) float g_part[SK_QKV * Tn * H3n];  // covers sk4 out-proj too

__device__ __forceinline__ uint32_t f2tf32(float f) {
    uint32_t u;
    asm("cvt.rna.tf32.f32 %0, %1;" : "=r"(u) : "f"(f));
    return u;
}

__device__ __forceinline__ void mma_tf32(float* c, const uint32_t* a, const uint32_t* b) {
    asm volatile(
        "mma.sync.aligned.m16n8k8.row.col.f32.tf32.tf32.f32 "
        "{%0,%1,%2,%3}, {%4,%5,%6,%7}, {%8,%9}, {%0,%1,%2,%3};"
        : "+f"(c[0]), "+f"(c[1]), "+f"(c[2]), "+f"(c[3])
        : "r"(a[0]), "r"(a[1]), "r"(a[2]), "r"(a[3]), "r"(b[0]), "r"(b[1]));
}

// ---------------------------------------------------------------------------
// Split-K TF32 GEMM: P[z] = A[M,Kslice] @ B[N,Kslice]^T.  (R10-proven.)
__global__ void gemm_tf32_splitk(const float* __restrict__ A, const float* __restrict__ B,
                                 float* __restrict__ P, int M, int N, int K, int kps) {
    __shared__ uint32_t As[2][64][GKS];
    __shared__ uint32_t Bs[2][64][GKS];

    const int tid = threadIdx.x;
    const int wid = tid >> 5;
    const int lane = tid & 31;
    const int g = lane >> 2;
    const int t = lane & 3;

    const int bm = blockIdx.y * 64;
    const int bn = blockIdx.x * 64;
    const int wm = (wid >> 1) * 16;
    const int wn = (wid & 1) * 32;

    const int kbeg = blockIdx.z * kps;
    const int kend = kbeg + kps;

    float acc[4][4];
    #pragma unroll
    for (int ni = 0; ni < 4; ni++)
        #pragma unroll
        for (int r = 0; r < 4; r++) acc[ni][r] = 0.f;

    const int ldr = tid >> 3;
    const int ldc = (tid & 7) * 4;

    uint32_t af[2][4];
    uint32_t bf[2][4][2];

    auto load_frags = [&](int b, int kb, int p) {
        af[p][0] = As[b][wm + g][kb + t];
        af[p][1] = As[b][wm + g + 8][kb + t];
        af[p][2] = As[b][wm + g][kb + t + 4];
        af[p][3] = As[b][wm + g + 8][kb + t + 4];
        #pragma unroll
        for (int ni = 0; ni < 4; ni++) {
            int n0 = wn + ni * 8 + g;
            bf[p][ni][0] = Bs[b][n0][kb + t];
            bf[p][ni][1] = Bs[b][n0][kb + t + 4];
        }
    };
    auto do_mma = [&](int p) {
        #pragma unroll
        for (int ni = 0; ni < 4; ni++) mma_tf32(acc[ni], af[p], bf[p][ni]);
    };

    float4 pa[2], pb[2];
    #pragma unroll
    for (int i = 0; i < 2; i++) {
        int r = ldr + i * 32;
        pa[i] = *(const float4*)(A + (size_t)(bm + r) * K + kbeg + ldc);
        pb[i] = *(const float4*)(B + (size_t)(bn + r) * K + kbeg + ldc);
    }

    int buf = 0;
    #pragma unroll
    for (int i = 0; i < 2; i++) {
        int r = ldr + i * 32;
        *(uint4*)&As[0][r][ldc] = make_uint4(f2tf32(pa[i].x), f2tf32(pa[i].y),
                                             f2tf32(pa[i].z), f2tf32(pa[i].w));
        *(uint4*)&Bs[0][r][ldc] = make_uint4(f2tf32(pb[i].x), f2tf32(pb[i].y),
                                             f2tf32(pb[i].z), f2tf32(pb[i].w));
    }
    __syncthreads();
    load_frags(buf, 0, 0);

    for (int k0 = kbeg; k0 < kend; k0 += 32) {
        const bool has_next = (k0 + 32) < kend;
        if (has_next) {
            #pragma unroll
            for (int i = 0; i < 2; i++) {
                int r = ldr + i * 32;
                pa[i] = *(const float4*)(A + (size_t)(bm + r) * K + k0 + 32 + ldc);
                pb[i] = *(const float4*)(B + (size_t)(bn + r) * K + k0 + 32 + ldc);
            }
        }

        load_frags(buf, 8, 1);  do_mma(0);
        load_frags(buf, 16, 0); do_mma(1);
        load_frags(buf, 24, 1); do_mma(0);
        do_mma(1);

        if (has_next) {
            int nb = buf ^ 1;
            #pragma unroll
            for (int i = 0; i < 2; i++) {
                int r = ldr + i * 32;
                *(uint4*)&As[nb][r][ldc] = make_uint4(f2tf32(pa[i].x), f2tf32(pa[i].y),
                                                      f2tf32(pa[i].z), f2tf32(pa[i].w));
                *(uint4*)&Bs[nb][r][ldc] = make_uint4(f2tf32(pb[i].x), f2tf32(pb[i].y),
                                                      f2tf32(pb[i].z), f2tf32(pb[i].w));
            }
            __syncthreads();
            buf = nb;
            load_frags(buf, 0, 0);
        }
    }

    float* Pz = P + (size_t)blockIdx.z * M * N;
    const int row0 = bm + wm + g;
    #pragma unroll
    for (int ni = 0; ni < 4; ni++) {
        int col0 = bn + wn + ni * 8 + 2 * t;
        *(float2*)&Pz[(size_t)row0 * N + col0]       = make_float2(acc[ni][0], acc[ni][1]);
        *(float2*)&Pz[(size_t)(row0 + 8) * N + col0] = make_float2(acc[ni][2], acc[ni][3]);
    }
}

// ---------------------------------------------------------------------------
// Fused attention. K tile and transposed-V tile SHARE one smem region:
// V is staged after the scores mma (K's last use), halving the footprint
// (136KB -> 84KB) so 2 blocks co-reside per SM.
// Reference's additive edge bias is constant across keys (softmax over NE
// sums to 1) — a softmax invariant, omitted exactly.
template <int SK>
__global__ void attn_fused_kernel(const float* __restrict__ part,
                                  const float* __restrict__ bias,
                                  float* __restrict__ o) {
    extern __shared__ float sm[];
    uint32_t* Qs = (uint32_t*)sm;          // [32][AKS] tf32
    uint32_t* Ks = Qs + 32 * AKS;          // [192][AKS] tf32 (scores phase)
    uint32_t* Vt = Ks;                     // [64][VS]  tf32 transposed (PV phase, overlaid)
    float* Pm = (float*)(Ks + 192 * AKS);  // [32][PP]  scores, then tf32 P

    const int qt = blockIdx.x;   // 0..5
    const int h  = blockIdx.y;   // 0..15
    const int t  = threadIdx.x;  // 0..255
    const int wid = t >> 5;
    const int lane = t & 31;
    const int g = lane >> 2;
    const int tt = lane & 3;
    const size_t MN = (size_t)Tn * H3n;

    // ---- stage Q and K: sum SK split-K partials + bias, convert to tf32 ----
    #pragma unroll
    for (int i = t; i < 32 * 16; i += 256) {
        int r = i >> 4, c = (i & 15) * 4;
        size_t idx = (size_t)(qt * 32 + r) * H3n + h * HDn + c;
        float4 bb = *(const float4*)&bias[h * HDn + c];
        float4 a = *(const float4*)&part[idx];
        #pragma unroll
        for (int z = 1; z < SK; z++) {
            float4 p = *(const float4*)&part[z * MN + idx];
            a.x += p.x; a.y += p.y; a.z += p.z; a.w += p.w;
        }
        *(uint4*)&Qs[r * AKS + c] = make_uint4(
            f2tf32(a.x + bb.x), f2tf32(a.y + bb.y),
            f2tf32(a.z + bb.z), f2tf32(a.w + bb.w));
    }
    #pragma unroll
    for (int i = t; i < 192 * 16; i += 256) {
        int r = i >> 4, c = (i & 15) * 4;
        size_t idx = (size_t)r * H3n + Hn + h * HDn + c;
        float4 bb = *(const float4*)&bias[Hn + h * HDn + c];
        float4 a = *(const float4*)&part[idx];
        #pragma unroll
        for (int z = 1; z < SK; z++) {
            float4 p = *(const float4*)&part[z * MN + idx];
            a.x += p.x; a.y += p.y; a.z += p.z; a.w += p.w;
        }
        *(uint4*)&Ks[r * AKS + c] = make_uint4(
            f2tf32(a.x + bb.x), f2tf32(a.y + bb.y),
            f2tf32(a.z + bb.z), f2tf32(a.w + bb.w));
    }
    __syncthreads();

    // ---- scores via tf32 mma (ping-pong fragment pipeline over 8 ks) ----
    {
        const int mi = wid & 1;
        const int nq = wid >> 1;
        float acc[6][4];
        #pragma unroll
        for (int j = 0; j < 6; j++)
            #pragma unroll
            for (int r = 0; r < 4; r++) acc[j][r] = 0.f;

        uint32_t qf[2][4];
        uint32_t kf[2][6][2];
        auto load_sf = [&](int kb, int p) {
            qf[p][0] = Qs[(mi * 16 + g) * AKS + kb + tt];
            qf[p][1] = Qs[(mi * 16 + g + 8) * AKS + kb + tt];
            qf[p][2] = Qs[(mi * 16 + g) * AKS + kb + tt + 4];
            qf[p][3] = Qs[(mi * 16 + g + 8) * AKS + kb + tt + 4];
            #pragma unroll
            for (int j = 0; j < 6; j++) {
                int n0 = (nq * 6 + j) * 8 + g;
                kf[p][j][0] = Ks[n0 * AKS + kb + tt];
                kf[p][j][1] = Ks[n0 * AKS + kb + tt + 4];
            }
        };

        load_sf(0, 0);
        #pragma unroll
        for (int ks = 0; ks < 8; ks++) {
            const int p = ks & 1;
            if (ks < 7) load_sf((ks + 1) * 8, p ^ 1);
            #pragma unroll
            for (int j = 0; j < 6; j++) mma_tf32(acc[j], qf[p], kf[p][j]);
        }

        const int row0 = mi * 16 + g;
        #pragma unroll
        for (int j = 0; j < 6; j++) {
            int col0 = (nq * 6 + j) * 8 + 2 * tt;
            *(float2*)&Pm[row0 * PP + col0] =
                make_float2(acc[j][0] * 0.125f, acc[j][1] * 0.125f);
            *(float2*)&Pm[(row0 + 8) * PP + col0] =
                make_float2(acc[j][2] * 0.125f, acc[j][3] * 0.125f);
        }
    }
    __syncthreads();   // scores done: K region dead, Pm valid

    // ---- stage Vt into the (dead) K region, then softmax ----
    #pragma unroll
    for (int i = t; i < 192 * 16; i += 256) {
        int r = i >> 4, c = (i & 15) * 4;
        size_t idx = (size_t)r * H3n + 2 * Hn + h * HDn + c;
        float4 bb = *(const float4*)&bias[2 * Hn + h * HDn + c];
        float4 a = *(const float4*)&part[idx];
        #pragma unroll
        for (int z = 1; z < SK; z++) {
            float4 p = *(const float4*)&part[z * MN + idx];
            a.x += p.x; a.y += p.y; a.z += p.z; a.w += p.w;
        }
        Vt[(c + 0) * VS + r] = f2tf32(a.x + bb.x);
        Vt[(c + 1) * VS + r] = f2tf32(a.y + bb.y);
        Vt[(c + 2) * VS + r] = f2tf32(a.z + bb.z);
        Vt[(c + 3) * VS + r] = f2tf32(a.w + bb.w);
    }

    // softmax: fold 1/sum into P, store tf32 bits (writes Pm only)
    {
        uint32_t* Pmu = (uint32_t*)Pm;
        for (int r = wid * 4; r < wid * 4 + 4; r++) {
            float v[6];
            float mx = -1e30f;
            #pragma unroll
            for (int i = 0; i < 6; i++) {
                v[i] = Pm[r * PP + lane + 32 * i];
                mx = fmaxf(mx, v[i]);
            }
            #pragma unroll
            for (int off = 16; off > 0; off >>= 1)
                mx = fmaxf(mx, __shfl_xor_sync(0xffffffffu, mx, off));
            float sum = 0.f;
            #pragma unroll
            for (int i = 0; i < 6; i++) {
                v[i] = expf(v[i] - mx);
                sum += v[i];
            }
            #pragma unroll
            for (int off = 16; off > 0; off >>= 1)
                sum += __shfl_xor_sync(0xffffffffu, sum, off);
            float inv = 1.f / sum;
            #pragma unroll
            for (int i = 0; i < 6; i++)
                Pmu[r * PP + lane + 32 * i] = f2tf32(v[i] * inv);
        }
    }
    __syncthreads();

    // ---- PV via tf32 mma (ping-pong fragment pipeline over 24 kt) ----
    {
        const uint32_t* Pmu = (const uint32_t*)Pm;
        const int mi = wid & 1;
        const int nd = wid >> 1;
        float acc[2][4];
        #pragma unroll
        for (int jj = 0; jj < 2; jj++)
            #pragma unroll
            for (int r = 0; r < 4; r++) acc[jj][r] = 0.f;

        uint32_t pf[2][4];
        uint32_t vf[2][2][2];
        auto load_pv = [&](int kb, int p) {
            pf[p][0] = Pmu[(mi * 16 + g) * PP + kb + tt];
            pf[p][1] = Pmu[(mi * 16 + g + 8) * PP + kb + tt];
            pf[p][2] = Pmu[(mi * 16 + g) * PP + kb + tt + 4];
            pf[p][3] = Pmu[(mi * 16 + g + 8) * PP + kb + tt + 4];
            #pragma unroll
            for (int jj = 0; jj < 2; jj++) {
                int n0 = (nd * 2 + jj) * 8 + g;
                vf[p][jj][0] = Vt[n0 * VS + kb + tt];
                vf[p][jj][1] = Vt[n0 * VS + kb + tt + 4];
            }
        };

        load_pv(0, 0);
        #pragma unroll
        for (int kt = 0; kt < 24; kt++) {
            const int p = kt & 1;
            if (kt < 23) load_pv((kt + 1) * 8, p ^ 1);
            #pragma unroll
            for (int jj = 0; jj < 2; jj++) mma_tf32(acc[jj], pf[p], vf[p][jj]);
        }

        const int row0 = qt * 32 + mi * 16 + g;
        #pragma unroll
        for (int jj = 0; jj < 2; jj++) {
            int col0 = h * HDn + (nd * 2 + jj) * 8 + 2 * tt;
            *(float2*)&o[(size_t)row0 * Hn + col0]       = make_float2(acc[jj][0], acc[jj][1]);
            *(float2*)&o[(size_t)(row0 + 8) * Hn + col0] = make_float2(acc[jj][2], acc[jj][3]);
        }
    }
}

// ---------------------------------------------------------------------------
// x[t,:] = res[t,:] + LN(sum_z part[z] + bias) * g + b   (block-per-row)
template <int SK>
__global__ void ln_residual_fused(const float* __restrict__ part,
                                  const float* __restrict__ bias,
                                  const float* __restrict__ g,
                                  const float* __restrict__ b,
                                  const float* __restrict__ res,
                                  float* __restrict__ x) {
    const int t = blockIdx.x;
    const int tid = threadIdx.x;
    const size_t MN = (size_t)Tn * Hn;
    const size_t base = (size_t)t * Hn + tid * 4;

    float4 v = *(const float4*)&part[base];
    #pragma unroll
    for (int z = 1; z < SK; z++) {
        float4 p = *(const float4*)&part[z * MN + base];
        v.x += p.x; v.y += p.y; v.z += p.z; v.w += p.w;
    }
    float4 bb = *(const float4*)&bias[tid * 4];
    v.x += bb.x; v.y += bb.y; v.z += bb.z; v.w += bb.w;

    float4 go = *(const float4*)&g[tid * 4];
    float4 bo = *(const float4*)&b[tid * 4];
    float4 ro = *(const float4*)&res[base];

    float sum = v.x + v.y + v.z + v.w;
    float sq = v.x * v.x + v.y * v.y + v.z * v.z + v.w * v.w;

    __shared__ float s1[8], s2[8];
    #pragma unroll
    for (int off = 16; off > 0; off >>= 1) {
        sum += __shfl_xor_sync(0xffffffffu, sum, off);
        sq  += __shfl_xor_sync(0xffffffffu, sq, off);
    }
    if ((tid & 31) == 0) { s1[tid >> 5] = sum; s2[tid >> 5] = sq; }
    __syncthreads();
    float ts = 0.f, tq = 0.f;
    #pragma unroll
    for (int w = 0; w < 8; w++) { ts += s1[w]; tq += s2[w]; }

    float mean = ts * (1.f / Hn);
    float var = tq * (1.f / Hn) - mean * mean;
    float r = rsqrtf(var + 1e-5f);

    float4 xo;
    xo.x = ro.x + (v.x - mean) * r * go.x + bo.x;
    xo.y = ro.y + (v.y - mean) * r * go.y + bo.y;
    xo.z = ro.z + (v.z - mean) * r * go.z + bo.z;
    xo.w = ro.w + (v.w - mean) * r * go.w + bo.w;
    *(float4*)&x[base] = xo;
}

// ---------------------------------------------------------------------------
extern "C" void kernel_launch(void* const* d_in, const int* in_sizes, int n_in,
                              void* d_out, int out_size) {
    const float* nodes     = (const float*)d_in[0];
    const float* mha_in_w  = (const float*)d_in[14];
    const float* mha_in_b  = (const float*)d_in[15];
    const float* mha_out_w = (const float*)d_in[16];
    const float* mha_out_b = (const float*)d_in[17];
    const float* mha_ln_g  = (const float*)d_in[18];
    const float* mha_ln_b  = (const float*)d_in[19];
    float* x = (float*)d_out;

    float *o, *part;
    cudaGetSymbolAddress((void**)&o,    g_o);
    cudaGetSymbolAddress((void**)&part, g_part);

    static bool attr_done = false;
    if (!attr_done) {
        cudaFuncSetAttribute(attn_fused_kernel<SK_QKV>,
                             cudaFuncAttributeMaxDynamicSharedMemorySize,
                             ATTN_SMEM_BYTES);
        attr_done = true;
    }

    for (int l = 0; l < 2; l++) {
        const float* Wi = mha_in_w  + (size_t)l * H3n * Hn;
        const float* bi = mha_in_b  + (size_t)l * H3n;
        const float* Wo = mha_out_w + (size_t)l * Hn * Hn;
        const float* bo = mha_out_b + (size_t)l * Hn;
        const float* lg = mha_ln_g  + (size_t)l * Hn;
        const float* lb = mha_ln_b  + (size_t)l * Hn;

        const float* xin  = (l == 0) ? nodes : x;
        const float* resv = (l == 0) ? nodes : x;

        // qkv partials (sk=2): grid 48x3x2 = 288 blocks
        gemm_tf32_splitk<<<dim3(H3n / 64, Tn / 64, SK_QKV), 256>>>(
            xin, Wi, part, Tn, H3n, Hn, Hn / SK_QKV);
        // attention (consumes partials + bias directly)
        attn_fused_kernel<SK_QKV><<<dim3(Tn / 32, NHn), 256, ATTN_SMEM_BYTES>>>(part, bi, o);
        // out-proj partials (sk=4): grid 16x3x4 = 192 blocks
        gemm_tf32_splitk<<<dim3(Hn / 64, Tn / 64, SK_OUT), 256>>>(
            o, Wo, part, Tn, Hn, Hn, Hn / SK_OUT);
        // fused reduce + bias + LN + residual (block-per-row)
        ln_residual_fused<SK_OUT><<<Tn, 256>>>(part, bo, lg, lb, resv, x);
    }
}

// round 15
// speedup vs baseline: 1.4914x; 1.4914x over previous
#include <cuda_runtime.h>
#include <cstdint>

#define Tn 192
#define Hn 1024
#define NHn 16
#define HDn 64
#define H3n 3072

#define SK_QKV 2
#define SK_OUT 4

#define GKS 36   // smem row stride (words) for GEMM tiles (BK=32 wide)
#define AKS 68   // smem row stride (words) for attention Q/K tiles (64 wide)
#define VS  196  // smem row stride for transposed V (192 keys wide)
#define PP  196  // smem row stride for score/P matrix
#define ATTN_SMEM_BYTES ((32*AKS + 192*AKS + 64*VS + 32*PP) * 4)

// Scratch (device globals — no allocation allowed)
__device__ __align__(16) float g_o[Tn * Hn];
__device__ __align__(16) float g_part[SK_QKV * Tn * H3n];   // covers sk4 out-proj too
__device__ __align__(16) uint32_t g_qkvp[Tn * H3n];          // packed tf32 qkv (+bias)

__device__ __forceinline__ uint32_t f2tf32(float f) {
    uint32_t u;
    asm("cvt.rna.tf32.f32 %0, %1;" : "=r"(u) : "f"(f));
    return u;
}

__device__ __forceinline__ void mma_tf32(float* c, const uint32_t* a, const uint32_t* b) {
    asm volatile(
        "mma.sync.aligned.m16n8k8.row.col.f32.tf32.tf32.f32 "
        "{%0,%1,%2,%3}, {%4,%5,%6,%7}, {%8,%9}, {%0,%1,%2,%3};"
        : "+f"(c[0]), "+f"(c[1]), "+f"(c[2]), "+f"(c[3])
        : "r"(a[0]), "r"(a[1]), "r"(a[2]), "r"(a[3]), "r"(b[0]), "r"(b[1]));
}

__device__ __forceinline__ uint32_t smem_u32(const void* p) {
    uint32_t a;
    asm("{ .reg .u64 t; cvta.to.shared.u64 t, %1; cvt.u32.u64 %0, t; }"
        : "=r"(a) : "l"(p));
    return a;
}

__device__ __forceinline__ void cp_async16(uint32_t saddr, const void* g) {
    asm volatile("cp.async.cg.shared.global [%0], [%1], 16;" :: "r"(saddr), "l"(g));
}

// ---------------------------------------------------------------------------
// Split-K TF32 GEMM: P[z] = A[M,Kslice] @ B[N,Kslice]^T.  (R10-proven, unchanged.)
__global__ void gemm_tf32_splitk(const float* __restrict__ A, const float* __restrict__ B,
                                 float* __restrict__ P, int M, int N, int K, int kps) {
    __shared__ uint32_t As[2][64][GKS];
    __shared__ uint32_t Bs[2][64][GKS];

    const int tid = threadIdx.x;
    const int wid = tid >> 5;
    const int lane = tid & 31;
    const int g = lane >> 2;
    const int t = lane & 3;

    const int bm = blockIdx.y * 64;
    const int bn = blockIdx.x * 64;
    const int wm = (wid >> 1) * 16;
    const int wn = (wid & 1) * 32;

    const int kbeg = blockIdx.z * kps;
    const int kend = kbeg + kps;

    float acc[4][4];
    #pragma unroll
    for (int ni = 0; ni < 4; ni++)
        #pragma unroll
        for (int r = 0; r < 4; r++) acc[ni][r] = 0.f;

    const int ldr = tid >> 3;
    const int ldc = (tid & 7) * 4;

    uint32_t af[2][4];
    uint32_t bf[2][4][2];

    auto load_frags = [&](int b, int kb, int p) {
        af[p][0] = As[b][wm + g][kb + t];
        af[p][1] = As[b][wm + g + 8][kb + t];
        af[p][2] = As[b][wm + g][kb + t + 4];
        af[p][3] = As[b][wm + g + 8][kb + t + 4];
        #pragma unroll
        for (int ni = 0; ni < 4; ni++) {
            int n0 = wn + ni * 8 + g;
            bf[p][ni][0] = Bs[b][n0][kb + t];
            bf[p][ni][1] = Bs[b][n0][kb + t + 4];
        }
    };
    auto do_mma = [&](int p) {
        #pragma unroll
        for (int ni = 0; ni < 4; ni++) mma_tf32(acc[ni], af[p], bf[p][ni]);
    };

    float4 pa[2], pb[2];
    #pragma unroll
    for (int i = 0; i < 2; i++) {
        int r = ldr + i * 32;
        pa[i] = *(const float4*)(A + (size_t)(bm + r) * K + kbeg + ldc);
        pb[i] = *(const float4*)(B + (size_t)(bn + r) * K + kbeg + ldc);
    }

    int buf = 0;
    #pragma unroll
    for (int i = 0; i < 2; i++) {
        int r = ldr + i * 32;
        *(uint4*)&As[0][r][ldc] = make_uint4(f2tf32(pa[i].x), f2tf32(pa[i].y),
                                             f2tf32(pa[i].z), f2tf32(pa[i].w));
        *(uint4*)&Bs[0][r][ldc] = make_uint4(f2tf32(pb[i].x), f2tf32(pb[i].y),
                                             f2tf32(pb[i].z), f2tf32(pb[i].w));
    }
    __syncthreads();
    load_frags(buf, 0, 0);

    for (int k0 = kbeg; k0 < kend; k0 += 32) {
        const bool has_next = (k0 + 32) < kend;
        if (has_next) {
            #pragma unroll
            for (int i = 0; i < 2; i++) {
                int r = ldr + i * 32;
                pa[i] = *(const float4*)(A + (size_t)(bm + r) * K + k0 + 32 + ldc);
                pb[i] = *(const float4*)(B + (size_t)(bn + r) * K + k0 + 32 + ldc);
            }
        }

        load_frags(buf, 8, 1);  do_mma(0);
        load_frags(buf, 16, 0); do_mma(1);
        load_frags(buf, 24, 1); do_mma(0);
        do_mma(1);

        if (has_next) {
            int nb = buf ^ 1;
            #pragma unroll
            for (int i = 0; i < 2; i++) {
                int r = ldr + i * 32;
                *(uint4*)&As[nb][r][ldc] = make_uint4(f2tf32(pa[i].x), f2tf32(pa[i].y),
                                                      f2tf32(pa[i].z), f2tf32(pa[i].w));
                *(uint4*)&Bs[nb][r][ldc] = make_uint4(f2tf32(pb[i].x), f2tf32(pb[i].y),
                                                      f2tf32(pb[i].z), f2tf32(pb[i].w));
            }
            __syncthreads();
            buf = nb;
            load_frags(buf, 0, 0);
        }
    }

    float* Pz = P + (size_t)blockIdx.z * M * N;
    const int row0 = bm + wm + g;
    #pragma unroll
    for (int ni = 0; ni < 4; ni++) {
        int col0 = bn + wn + ni * 8 + 2 * t;
        *(float2*)&Pz[(size_t)row0 * N + col0]       = make_float2(acc[ni][0], acc[ni][1]);
        *(float2*)&Pz[(size_t)(row0 + 8) * N + col0] = make_float2(acc[ni][2], acc[ni][3]);
    }
}

// ---------------------------------------------------------------------------
// Pack: qkvp[i] = tf32(sum_z part[z][i] + bias[col])  — done ONCE instead of
// redundantly inside every attention block (same arithmetic order).
template <int SK>
__global__ void qkv_pack(const float* __restrict__ part, const float* __restrict__ bias,
                         uint32_t* __restrict__ out) {
    const int i = (blockIdx.x * blockDim.x + threadIdx.x) * 4;
    const size_t MN = (size_t)Tn * H3n;
    float4 a = *(const float4*)&part[i];
    #pragma unroll
    for (int z = 1; z < SK; z++) {
        float4 p = *(const float4*)&part[z * MN + i];
        a.x += p.x; a.y += p.y; a.z += p.z; a.w += p.w;
    }
    float4 bb = *(const float4*)&bias[i % H3n];
    *(uint4*)&out[i] = make_uint4(f2tf32(a.x + bb.x), f2tf32(a.y + bb.y),
                                  f2tf32(a.z + bb.z), f2tf32(a.w + bb.w));
}

// ---------------------------------------------------------------------------
// Fused attention (R10 layout: Q/K/Vt staged upfront, separate regions).
// Staging is now pure copy from the packed tf32 buffer: Q/K via cp.async,
// Vt via load-scatter. Scores AND PV via tf32 mma with fragment ping-pong.
// Reference's additive edge bias is constant across keys (softmax over NE
// sums to 1) — a softmax invariant, omitted exactly.
__global__ void attn_fused_kernel(const uint32_t* __restrict__ qkvp,
                                  float* __restrict__ o) {
    extern __shared__ float sm[];
    uint32_t* Qs = (uint32_t*)sm;          // [32][AKS] tf32
    uint32_t* Ks = Qs + 32 * AKS;          // [192][AKS] tf32
    uint32_t* Vt = Ks + 192 * AKS;         // [64][VS]  tf32, transposed (dim-major)
    float* Pm = (float*)(Vt + 64 * VS);    // [32][PP]  scores, then tf32 P

    const int qt = blockIdx.x;   // 0..5
    const int h  = blockIdx.y;   // 0..15
    const int t  = threadIdx.x;  // 0..255
    const int wid = t >> 5;
    const int lane = t & 31;
    const int g = lane >> 2;
    const int tt = lane & 3;

    // ---- stage Q and K via cp.async (pure 16B copies) ----
    #pragma unroll
    for (int i = t; i < 32 * 16; i += 256) {
        int r = i >> 4, c = (i & 15) * 4;
        cp_async16(smem_u32(&Qs[r * AKS + c]),
                   &qkvp[(size_t)(qt * 32 + r) * H3n + h * HDn + c]);
    }
    #pragma unroll
    for (int i = t; i < 192 * 16; i += 256) {
        int r = i >> 4, c = (i & 15) * 4;
        cp_async16(smem_u32(&Ks[r * AKS + c]),
                   &qkvp[(size_t)r * H3n + Hn + h * HDn + c]);
    }
    asm volatile("cp.async.commit_group;" ::: "memory");

    // ---- stage Vt (transposed scatter; overlaps the cp.async group) ----
    #pragma unroll
    for (int i = t; i < 192 * 16; i += 256) {
        int r = i >> 4, c = (i & 15) * 4;
        uint4 v = *(const uint4*)&qkvp[(size_t)r * H3n + 2 * Hn + h * HDn + c];
        Vt[(c + 0) * VS + r] = v.x;
        Vt[(c + 1) * VS + r] = v.y;
        Vt[(c + 2) * VS + r] = v.z;
        Vt[(c + 3) * VS + r] = v.w;
    }
    asm volatile("cp.async.wait_group 0;" ::: "memory");
    __syncthreads();

    // ---- scores via tf32 mma (ping-pong fragment pipeline over 8 ks) ----
    {
        const int mi = wid & 1;
        const int nq = wid >> 1;
        float acc[6][4];
        #pragma unroll
        for (int j = 0; j < 6; j++)
            #pragma unroll
            for (int r = 0; r < 4; r++) acc[j][r] = 0.f;

        uint32_t qf[2][4];
        uint32_t kf[2][6][2];
        auto load_sf = [&](int kb, int p) {
            qf[p][0] = Qs[(mi * 16 + g) * AKS + kb + tt];
            qf[p][1] = Qs[(mi * 16 + g + 8) * AKS + kb + tt];
            qf[p][2] = Qs[(mi * 16 + g) * AKS + kb + tt + 4];
            qf[p][3] = Qs[(mi * 16 + g + 8) * AKS + kb + tt + 4];
            #pragma unroll
            for (int j = 0; j < 6; j++) {
                int n0 = (nq * 6 + j) * 8 + g;
                kf[p][j][0] = Ks[n0 * AKS + kb + tt];
                kf[p][j][1] = Ks[n0 * AKS + kb + tt + 4];
            }
        };

        load_sf(0, 0);
        #pragma unroll
        for (int ks = 0; ks < 8; ks++) {
            const int p = ks & 1;
            if (ks < 7) load_sf((ks + 1) * 8, p ^ 1);
            #pragma unroll
            for (int j = 0; j < 6; j++) mma_tf32(acc[j], qf[p], kf[p][j]);
        }

        const int row0 = mi * 16 + g;
        #pragma unroll
        for (int j = 0; j < 6; j++) {
            int col0 = (nq * 6 + j) * 8 + 2 * tt;
            *(float2*)&Pm[row0 * PP + col0] =
                make_float2(acc[j][0] * 0.125f, acc[j][1] * 0.125f);
            *(float2*)&Pm[(row0 + 8) * PP + col0] =
                make_float2(acc[j][2] * 0.125f, acc[j][3] * 0.125f);
        }
    }
    __syncthreads();

    // ---- softmax: fold 1/sum into P, store tf32 bits ----
    {
        uint32_t* Pmu = (uint32_t*)Pm;
        for (int r = wid * 4; r < wid * 4 + 4; r++) {
            float v[6];
            float mx = -1e30f;
            #pragma unroll
            for (int i = 0; i < 6; i++) {
                v[i] = Pm[r * PP + lane + 32 * i];
                mx = fmaxf(mx, v[i]);
            }
            #pragma unroll
            for (int off = 16; off > 0; off >>= 1)
                mx = fmaxf(mx, __shfl_xor_sync(0xffffffffu, mx, off));
            float sum = 0.f;
            #pragma unroll
            for (int i = 0; i < 6; i++) {
                v[i] = expf(v[i] - mx);
                sum += v[i];
            }
            #pragma unroll
            for (int off = 16; off > 0; off >>= 1)
                sum += __shfl_xor_sync(0xffffffffu, sum, off);
            float inv = 1.f / sum;
            #pragma unroll
            for (int i = 0; i < 6; i++)
                Pmu[r * PP + lane + 32 * i] = f2tf32(v[i] * inv);
        }
    }
    __syncthreads();

    // ---- PV via tf32 mma (ping-pong fragment pipeline over 24 kt) ----
    {
        const uint32_t* Pmu = (const uint32_t*)Pm;
        const int mi = wid & 1;
        const int nd = wid >> 1;
        float acc[2][4];
        #pragma unroll
        for (int jj = 0; jj < 2; jj++)
            #pragma unroll
            for (int r = 0; r < 4; r++) acc[jj][r] = 0.f;

        uint32_t pf[2][4];
        uint32_t vf[2][2][2];
        auto load_pv = [&](int kb, int p) {
            pf[p][0] = Pmu[(mi * 16 + g) * PP + kb + tt];
            pf[p][1] = Pmu[(mi * 16 + g + 8) * PP + kb + tt];
            pf[p][2] = Pmu[(mi * 16 + g) * PP + kb + tt + 4];
            pf[p][3] = Pmu[(mi * 16 + g + 8) * PP + kb + tt + 4];
            #pragma unroll
            for (int jj = 0; jj < 2; jj++) {
                int n0 = (nd * 2 + jj) * 8 + g;
                vf[p][jj][0] = Vt[n0 * VS + kb + tt];
                vf[p][jj][1] = Vt[n0 * VS + kb + tt + 4];
            }
        };

        load_pv(0, 0);
        #pragma unroll
        for (int kt = 0; kt < 24; kt++) {
            const int p = kt & 1;
            if (kt < 23) load_pv((kt + 1) * 8, p ^ 1);
            #pragma unroll
            for (int jj = 0; jj < 2; jj++) mma_tf32(acc[jj], pf[p], vf[p][jj]);
        }

        const int row0 = qt * 32 + mi * 16 + g;
        #pragma unroll
        for (int jj = 0; jj < 2; jj++) {
            int col0 = h * HDn + (nd * 2 + jj) * 8 + 2 * tt;
            *(float2*)&o[(size_t)row0 * Hn + col0]       = make_float2(acc[jj][0], acc[jj][1]);
            *(float2*)&o[(size_t)(row0 + 8) * Hn + col0] = make_float2(acc[jj][2], acc[jj][3]);
        }
    }
}

// ---------------------------------------------------------------------------
// x[t,:] = res[t,:] + LN(sum_z part[z] + bias) * g + b   (block-per-row, R10)
template <int SK>
__global__ void ln_residual_fused(const float* __restrict__ part,
                                  const float* __restrict__ bias,
                                  const float* __restrict__ g,
                                  const float* __restrict__ b,
                                  const float* __restrict__ res,
                                  float* __restrict__ x) {
    const int t = blockIdx.x;
    const int tid = threadIdx.x;
    const size_t MN = (size_t)Tn * Hn;
    const size_t base = (size_t)t * Hn + tid * 4;

    float4 v = *(const float4*)&part[base];
    #pragma unroll
    for (int z = 1; z < SK; z++) {
        float4 p = *(const float4*)&part[z * MN + base];
        v.x += p.x; v.y += p.y; v.z += p.z; v.w += p.w;
    }
    float4 bb = *(const float4*)&bias[tid * 4];
    v.x += bb.x; v.y += bb.y; v.z += bb.z; v.w += bb.w;

    float sum = v.x + v.y + v.z + v.w;
    float sq = v.x * v.x + v.y * v.y + v.z * v.z + v.w * v.w;

    __shared__ float s1[8], s2[8];
    #pragma unroll
    for (int off = 16; off > 0; off >>= 1) {
        sum += __shfl_xor_sync(0xffffffffu, sum, off);
        sq  += __shfl_xor_sync(0xffffffffu, sq, off);
    }
    if ((tid & 31) == 0) { s1[tid >> 5] = sum; s2[tid >> 5] = sq; }
    __syncthreads();
    float ts = 0.f, tq = 0.f;
    #pragma unroll
    for (int w = 0; w < 8; w++) { ts += s1[w]; tq += s2[w]; }

    float mean = ts * (1.f / Hn);
    float var = tq * (1.f / Hn) - mean * mean;
    float r = rsqrtf(var + 1e-5f);

    float4 go = *(const float4*)&g[tid * 4];
    float4 bo = *(const float4*)&b[tid * 4];
    float4 ro = *(const float4*)&res[base];
    float4 xo;
    xo.x = ro.x + (v.x - mean) * r * go.x + bo.x;
    xo.y = ro.y + (v.y - mean) * r * go.y + bo.y;
    xo.z = ro.z + (v.z - mean) * r * go.z + bo.z;
    xo.w = ro.w + (v.w - mean) * r * go.w + bo.w;
    *(float4*)&x[base] = xo;
}

// ---------------------------------------------------------------------------
extern "C" void kernel_launch(void* const* d_in, const int* in_sizes, int n_in,
                              void* d_out, int out_size) {
    const float* nodes     = (const float*)d_in[0];
    const float* mha_in_w  = (const float*)d_in[14];
    const float* mha_in_b  = (const float*)d_in[15];
    const float* mha_out_w = (const float*)d_in[16];
    const float* mha_out_b = (const float*)d_in[17];
    const float* mha_ln_g  = (const float*)d_in[18];
    const float* mha_ln_b  = (const float*)d_in[19];
    float* x = (float*)d_out;

    float *o, *part;
    uint32_t* qkvp;
    cudaGetSymbolAddress((void**)&o,    g_o);
    cudaGetSymbolAddress((void**)&part, g_part);
    cudaGetSymbolAddress((void**)&qkvp, g_qkvp);

    static bool attr_done = false;
    if (!attr_done) {
        cudaFuncSetAttribute(attn_fused_kernel,
                             cudaFuncAttributeMaxDynamicSharedMemorySize,
                             ATTN_SMEM_BYTES);
        attr_done = true;
    }

    for (int l = 0; l < 2; l++) {
        const float* Wi = mha_in_w  + (size_t)l * H3n * Hn;
        const float* bi = mha_in_b  + (size_t)l * H3n;
        const float* Wo = mha_out_w + (size_t)l * Hn * Hn;
        const float* bo = mha_out_b + (size_t)l * Hn;
        const float* lg = mha_ln_g  + (size_t)l * Hn;
        const float* lb = mha_ln_b  + (size_t)l * Hn;

        const float* xin  = (l == 0) ? nodes : x;
        const float* resv = (l == 0) ? nodes : x;

        // qkv partials (sk=2): grid 48x3x2 = 288 blocks
        gemm_tf32_splitk<<<dim3(H3n / 64, Tn / 64, SK_QKV), 256>>>(
            xin, Wi, part, Tn, H3n, Hn, Hn / SK_QKV);
        // pack: reduce partials + bias + tf32 convert, once (576 blocks)
        qkv_pack<SK_QKV><<<(Tn * H3n / 4) / 256, 256>>>(part, bi, qkvp);
        // attention (pure-copy staging from packed buffer)
        attn_fused_kernel<<<dim3(Tn / 32, NHn), 256, ATTN_SMEM_BYTES>>>(qkvp, o);
        // out-proj partials (sk=4): grid 16x3x4 = 192 blocks
        gemm_tf32_splitk<<<dim3(Hn / 64, Tn / 64, SK_OUT), 256>>>(
            o, Wo, part, Tn, Hn, Hn, Hn / SK_OUT);
        // fused reduce + bias + LN + residual (block-per-row)
        ln_residual_fused<SK_OUT><<<Tn, 256>>>(part, bo, lg, lb, resv, x);
    }
}

// round 16
// speedup vs baseline: 1.4972x; 1.0039x over previous
#include <cuda_runtime.h>
#include <cstdint>

#define Tn 192
#define Hn 1024
#define NHn 16
#define HDn 64
#define H3n 3072

#define SK_QKV 2
#define SK_OUT 4

#define GKS 36   // smem row stride (words) for GEMM tiles (BK=32 wide)
#define AKS 68   // smem row stride (words) for attention Q/K tiles (64 wide)
#define VS  196  // smem row stride for transposed V (192 keys wide)
#define PP  196  // smem row stride for score/P matrix
#define ATTN_SMEM_BYTES ((32*AKS + 192*AKS + 64*VS + 32*PP) * 4)

// Scratch (device globals — no allocation allowed)
__device__ __align__(16) float g_o[Tn * Hn];
__device__ __align__(16) float g_part[SK_QKV * Tn * H3n];   // covers sk4 out-proj too
__device__ __align__(16) uint32_t g_qkvp[Tn * H3n];          // packed tf32 qkv (+bias)

__device__ __forceinline__ uint32_t f2tf32(float f) {
    uint32_t u;
    asm("cvt.rna.tf32.f32 %0, %1;" : "=r"(u) : "f"(f));
    return u;
}

__device__ __forceinline__ void mma_tf32(float* c, const uint32_t* a, const uint32_t* b) {
    asm volatile(
        "mma.sync.aligned.m16n8k8.row.col.f32.tf32.tf32.f32 "
        "{%0,%1,%2,%3}, {%4,%5,%6,%7}, {%8,%9}, {%0,%1,%2,%3};"
        : "+f"(c[0]), "+f"(c[1]), "+f"(c[2]), "+f"(c[3])
        : "r"(a[0]), "r"(a[1]), "r"(a[2]), "r"(a[3]), "r"(b[0]), "r"(b[1]));
}

__device__ __forceinline__ uint32_t smem_u32(const void* p) {
    uint32_t a;
    asm("{ .reg .u64 t; cvta.to.shared.u64 t, %1; cvt.u32.u64 %0, t; }"
        : "=r"(a) : "l"(p));
    return a;
}

__device__ __forceinline__ void cp_async16(uint32_t saddr, const void* g) {
    asm volatile("cp.async.cg.shared.global [%0], [%1], 16;" :: "r"(saddr), "l"(g));
}

// ---------------------------------------------------------------------------
// Split-K TF32 GEMM templated on the N block-tile width BN (64 or 32).
// P[z] = A[M,Kslice] @ B[N,Kslice]^T. 256 threads = 8 warps (4m x 2n),
// block tile 64xBN, warp tile 16x(BN/2), BK=32. Double-buffered smem +
// ping-pong register fragment pipeline. (BN=64 path is R10-proven.)
template <int BN>
__global__ void gemm_tf32_splitk(const float* __restrict__ A, const float* __restrict__ B,
                                 float* __restrict__ P, int M, int N, int K, int kps) {
    constexpr int NT = BN / 16;        // n-tiles (of 8 cols) per warp
    constexpr int NBL = BN / 32;       // B staging float4-loads per thread

    __shared__ uint32_t As[2][64][GKS];
    __shared__ uint32_t Bs[2][BN][GKS];

    const int tid = threadIdx.x;
    const int wid = tid >> 5;
    const int lane = tid & 31;
    const int g = lane >> 2;
    const int t = lane & 3;

    const int bm = blockIdx.y * 64;
    const int bn = blockIdx.x * BN;
    const int wm = (wid >> 1) * 16;
    const int wn = (wid & 1) * (BN / 2);

    const int kbeg = blockIdx.z * kps;
    const int kend = kbeg + kps;

    float acc[NT][4];
    #pragma unroll
    for (int ni = 0; ni < NT; ni++)
        #pragma unroll
        for (int r = 0; r < 4; r++) acc[ni][r] = 0.f;

    const int ldr = tid >> 3;
    const int ldc = (tid & 7) * 4;

    uint32_t af[2][4];
    uint32_t bf[2][NT][2];

    auto load_frags = [&](int b, int kb, int p) {
        af[p][0] = As[b][wm + g][kb + t];
        af[p][1] = As[b][wm + g + 8][kb + t];
        af[p][2] = As[b][wm + g][kb + t + 4];
        af[p][3] = As[b][wm + g + 8][kb + t + 4];
        #pragma unroll
        for (int ni = 0; ni < NT; ni++) {
            int n0 = wn + ni * 8 + g;
            bf[p][ni][0] = Bs[b][n0][kb + t];
            bf[p][ni][1] = Bs[b][n0][kb + t + 4];
        }
    };
    auto do_mma = [&](int p) {
        #pragma unroll
        for (int ni = 0; ni < NT; ni++) mma_tf32(acc[ni], af[p], bf[p][ni]);
    };

    float4 pa[2], pb[NBL];
    #pragma unroll
    for (int i = 0; i < 2; i++) {
        int r = ldr + i * 32;
        pa[i] = *(const float4*)(A + (size_t)(bm + r) * K + kbeg + ldc);
    }
    #pragma unroll
    for (int i = 0; i < NBL; i++) {
        int r = ldr + i * 32;
        pb[i] = *(const float4*)(B + (size_t)(bn + r) * K + kbeg + ldc);
    }

    int buf = 0;
    #pragma unroll
    for (int i = 0; i < 2; i++) {
        int r = ldr + i * 32;
        *(uint4*)&As[0][r][ldc] = make_uint4(f2tf32(pa[i].x), f2tf32(pa[i].y),
                                             f2tf32(pa[i].z), f2tf32(pa[i].w));
    }
    #pragma unroll
    for (int i = 0; i < NBL; i++) {
        int r = ldr + i * 32;
        *(uint4*)&Bs[0][r][ldc] = make_uint4(f2tf32(pb[i].x), f2tf32(pb[i].y),
                                             f2tf32(pb[i].z), f2tf32(pb[i].w));
    }
    __syncthreads();
    load_frags(buf, 0, 0);

    for (int k0 = kbeg; k0 < kend; k0 += 32) {
        const bool has_next = (k0 + 32) < kend;
        if (has_next) {
            #pragma unroll
            for (int i = 0; i < 2; i++) {
                int r = ldr + i * 32;
                pa[i] = *(const float4*)(A + (size_t)(bm + r) * K + k0 + 32 + ldc);
            }
            #pragma unroll
            for (int i = 0; i < NBL; i++) {
                int r = ldr + i * 32;
                pb[i] = *(const float4*)(B + (size_t)(bn + r) * K + k0 + 32 + ldc);
            }
        }

        // ping-pong fragment pipeline over the 4 ks steps
        load_frags(buf, 8, 1);  do_mma(0);
        load_frags(buf, 16, 0); do_mma(1);
        load_frags(buf, 24, 1); do_mma(0);
        do_mma(1);

        if (has_next) {
            int nb = buf ^ 1;
            #pragma unroll
            for (int i = 0; i < 2; i++) {
                int r = ldr + i * 32;
                *(uint4*)&As[nb][r][ldc] = make_uint4(f2tf32(pa[i].x), f2tf32(pa[i].y),
                                                      f2tf32(pa[i].z), f2tf32(pa[i].w));
            }
            #pragma unroll
            for (int i = 0; i < NBL; i++) {
                int r = ldr + i * 32;
                *(uint4*)&Bs[nb][r][ldc] = make_uint4(f2tf32(pb[i].x), f2tf32(pb[i].y),
                                                      f2tf32(pb[i].z), f2tf32(pb[i].w));
            }
            __syncthreads();
            buf = nb;
            load_frags(buf, 0, 0);
        }
    }

    float* Pz = P + (size_t)blockIdx.z * M * N;
    const int row0 = bm + wm + g;
    #pragma unroll
    for (int ni = 0; ni < NT; ni++) {
        int col0 = bn + wn + ni * 8 + 2 * t;
        *(float2*)&Pz[(size_t)row0 * N + col0]       = make_float2(acc[ni][0], acc[ni][1]);
        *(float2*)&Pz[(size_t)(row0 + 8) * N + col0] = make_float2(acc[ni][2], acc[ni][3]);
    }
}

// ---------------------------------------------------------------------------
// Pack: qkvp[i] = tf32(sum_z part[z][i] + bias[col])  (R15-proven.)
template <int SK>
__global__ void qkv_pack(const float* __restrict__ part, const float* __restrict__ bias,
                         uint32_t* __restrict__ out) {
    const int i = (blockIdx.x * blockDim.x + threadIdx.x) * 4;
    const size_t MN = (size_t)Tn * H3n;
    float4 a = *(const float4*)&part[i];
    #pragma unroll
    for (int z = 1; z < SK; z++) {
        float4 p = *(const float4*)&part[z * MN + i];
        a.x += p.x; a.y += p.y; a.z += p.z; a.w += p.w;
    }
    float4 bb = *(const float4*)&bias[i % H3n];
    *(uint4*)&out[i] = make_uint4(f2tf32(a.x + bb.x), f2tf32(a.y + bb.y),
                                  f2tf32(a.z + bb.z), f2tf32(a.w + bb.w));
}

// ---------------------------------------------------------------------------
// Fused attention (R15-proven: pure-copy staging from packed buffer).
// Reference's additive edge bias is constant across keys (softmax over NE
// sums to 1) — a softmax invariant, omitted exactly.
__global__ void attn_fused_kernel(const uint32_t* __restrict__ qkvp,
                                  float* __restrict__ o) {
    extern __shared__ float sm[];
    uint32_t* Qs = (uint32_t*)sm;          // [32][AKS] tf32
    uint32_t* Ks = Qs + 32 * AKS;          // [192][AKS] tf32
    uint32_t* Vt = Ks + 192 * AKS;         // [64][VS]  tf32, transposed (dim-major)
    float* Pm = (float*)(Vt + 64 * VS);    // [32][PP]  scores, then tf32 P

    const int qt = blockIdx.x;   // 0..5
    const int h  = blockIdx.y;   // 0..15
    const int t  = threadIdx.x;  // 0..255
    const int wid = t >> 5;
    const int lane = t & 31;
    const int g = lane >> 2;
    const int tt = lane & 3;

    // ---- stage Q and K via cp.async (pure 16B copies) ----
    #pragma unroll
    for (int i = t; i < 32 * 16; i += 256) {
        int r = i >> 4, c = (i & 15) * 4;
        cp_async16(smem_u32(&Qs[r * AKS + c]),
                   &qkvp[(size_t)(qt * 32 + r) * H3n + h * HDn + c]);
    }
    #pragma unroll
    for (int i = t; i < 192 * 16; i += 256) {
        int r = i >> 4, c = (i & 15) * 4;
        cp_async16(smem_u32(&Ks[r * AKS + c]),
                   &qkvp[(size_t)r * H3n + Hn + h * HDn + c]);
    }
    asm volatile("cp.async.commit_group;" ::: "memory");

    // ---- stage Vt (transposed scatter; overlaps the cp.async group) ----
    #pragma unroll
    for (int i = t; i < 192 * 16; i += 256) {
        int r = i >> 4, c = (i & 15) * 4;
        uint4 v = *(const uint4*)&qkvp[(size_t)r * H3n + 2 * Hn + h * HDn + c];
        Vt[(c + 0) * VS + r] = v.x;
        Vt[(c + 1) * VS + r] = v.y;
        Vt[(c + 2) * VS + r] = v.z;
        Vt[(c + 3) * VS + r] = v.w;
    }
    asm volatile("cp.async.wait_group 0;" ::: "memory");
    __syncthreads();

    // ---- scores via tf32 mma (ping-pong fragment pipeline over 8 ks) ----
    {
        const int mi = wid & 1;
        const int nq = wid >> 1;
        float acc[6][4];
        #pragma unroll
        for (int j = 0; j < 6; j++)
            #pragma unroll
            for (int r = 0; r < 4; r++) acc[j][r] = 0.f;

        uint32_t qf[2][4];
        uint32_t kf[2][6][2];
        auto load_sf = [&](int kb, int p) {
            qf[p][0] = Qs[(mi * 16 + g) * AKS + kb + tt];
            qf[p][1] = Qs[(mi * 16 + g + 8) * AKS + kb + tt];
            qf[p][2] = Qs[(mi * 16 + g) * AKS + kb + tt + 4];
            qf[p][3] = Qs[(mi * 16 + g + 8) * AKS + kb + tt + 4];
            #pragma unroll
            for (int j = 0; j < 6; j++) {
                int n0 = (nq * 6 + j) * 8 + g;
                kf[p][j][0] = Ks[n0 * AKS + kb + tt];
                kf[p][j][1] = Ks[n0 * AKS + kb + tt + 4];
            }
        };

        load_sf(0, 0);
        #pragma unroll
        for (int ks = 0; ks < 8; ks++) {
            const int p = ks & 1;
            if (ks < 7) load_sf((ks + 1) * 8, p ^ 1);
            #pragma unroll
            for (int j = 0; j < 6; j++) mma_tf32(acc[j], qf[p], kf[p][j]);
        }

        const int row0 = mi * 16 + g;
        #pragma unroll
        for (int j = 0; j < 6; j++) {
            int col0 = (nq * 6 + j) * 8 + 2 * tt;
            *(float2*)&Pm[row0 * PP + col0] =
                make_float2(acc[j][0] * 0.125f, acc[j][1] * 0.125f);
            *(float2*)&Pm[(row0 + 8) * PP + col0] =
                make_float2(acc[j][2] * 0.125f, acc[j][3] * 0.125f);
        }
    }
    __syncthreads();

    // ---- softmax: fold 1/sum into P, store tf32 bits ----
    {
        uint32_t* Pmu = (uint32_t*)Pm;
        for (int r = wid * 4; r < wid * 4 + 4; r++) {
            float v[6];
            float mx = -1e30f;
            #pragma unroll
            for (int i = 0; i < 6; i++) {
                v[i] = Pm[r * PP + lane + 32 * i];
                mx = fmaxf(mx, v[i]);
            }
            #pragma unroll
            for (int off = 16; off > 0; off >>= 1)
                mx = fmaxf(mx, __shfl_xor_sync(0xffffffffu, mx, off));
            float sum = 0.f;
            #pragma unroll
            for (int i = 0; i < 6; i++) {
                v[i] = expf(v[i] - mx);
                sum += v[i];
            }
            #pragma unroll
            for (int off = 16; off > 0; off >>= 1)
                sum += __shfl_xor_sync(0xffffffffu, sum, off);
            float inv = 1.f / sum;
            #pragma unroll
            for (int i = 0; i < 6; i++)
                Pmu[r * PP + lane + 32 * i] = f2tf32(v[i] * inv);
        }
    }
    __syncthreads();

    // ---- PV via tf32 mma (ping-pong fragment pipeline over 24 kt) ----
    {
        const uint32_t* Pmu = (const uint32_t*)Pm;
        const int mi = wid & 1;
        const int nd = wid >> 1;
        float acc[2][4];
        #pragma unroll
        for (int jj = 0; jj < 2; jj++)
            #pragma unroll
            for (int r = 0; r < 4; r++) acc[jj][r] = 0.f;

        uint32_t pf[2][4];
        uint32_t vf[2][2][2];
        auto load_pv = [&](int kb, int p) {
            pf[p][0] = Pmu[(mi * 16 + g) * PP + kb + tt];
            pf[p][1] = Pmu[(mi * 16 + g + 8) * PP + kb + tt];
            pf[p][2] = Pmu[(mi * 16 + g) * PP + kb + tt + 4];
            pf[p][3] = Pmu[(mi * 16 + g + 8) * PP + kb + tt + 4];
            #pragma unroll
            for (int jj = 0; jj < 2; jj++) {
                int n0 = (nd * 2 + jj) * 8 + g;
                vf[p][jj][0] = Vt[n0 * VS + kb + tt];
                vf[p][jj][1] = Vt[n0 * VS + kb + tt + 4];
            }
        };

        load_pv(0, 0);
        #pragma unroll
        for (int kt = 0; kt < 24; kt++) {
            const int p = kt & 1;
            if (kt < 23) load_pv((kt + 1) * 8, p ^ 1);
            #pragma unroll
            for (int jj = 0; jj < 2; jj++) mma_tf32(acc[jj], pf[p], vf[p][jj]);
        }

        const int row0 = qt * 32 + mi * 16 + g;
        #pragma unroll
        for (int jj = 0; jj < 2; jj++) {
            int col0 = h * HDn + (nd * 2 + jj) * 8 + 2 * tt;
            *(float2*)&o[(size_t)row0 * Hn + col0]       = make_float2(acc[jj][0], acc[jj][1]);
            *(float2*)&o[(size_t)(row0 + 8) * Hn + col0] = make_float2(acc[jj][2], acc[jj][3]);
        }
    }
}

// ---------------------------------------------------------------------------
// x[t,:] = res[t,:] + LN(sum_z part[z] + bias) * g + b   (block-per-row, R10)
template <int SK>
__global__ void ln_residual_fused(const float* __restrict__ part,
                                  const float* __restrict__ bias,
                                  const float* __restrict__ g,
                                  const float* __restrict__ b,
                                  const float* __restrict__ res,
                                  float* __restrict__ x) {
    const int t = blockIdx.x;
    const int tid = threadIdx.x;
    const size_t MN = (size_t)Tn * Hn;
    const size_t base = (size_t)t * Hn + tid * 4;

    float4 v = *(const float4*)&part[base];
    #pragma unroll
    for (int z = 1; z < SK; z++) {
        float4 p = *(const float4*)&part[z * MN + base];
        v.x += p.x; v.y += p.y; v.z += p.z; v.w += p.w;
    }
    float4 bb = *(const float4*)&bias[tid * 4];
    v.x += bb.x; v.y += bb.y; v.z += bb.z; v.w += bb.w;

    float sum = v.x + v.y + v.z + v.w;
    float sq = v.x * v.x + v.y * v.y + v.z * v.z + v.w * v.w;

    __shared__ float s1[8], s2[8];
    #pragma unroll
    for (int off = 16; off > 0; off >>= 1) {
        sum += __shfl_xor_sync(0xffffffffu, sum, off);
        sq  += __shfl_xor_sync(0xffffffffu, sq, off);
    }
    if ((tid & 31) == 0) { s1[tid >> 5] = sum; s2[tid >> 5] = sq; }
    __syncthreads();
    float ts = 0.f, tq = 0.f;
    #pragma unroll
    for (int w = 0; w < 8; w++) { ts += s1[w]; tq += s2[w]; }

    float mean = ts * (1.f / Hn);
    float var = tq * (1.f / Hn) - mean * mean;
    float r = rsqrtf(var + 1e-5f);

    float4 go = *(const float4*)&g[tid * 4];
    float4 bo = *(const float4*)&b[tid * 4];
    float4 ro = *(const float4*)&res[base];
    float4 xo;
    xo.x = ro.x + (v.x - mean) * r * go.x + bo.x;
    xo.y = ro.y + (v.y - mean) * r * go.y + bo.y;
    xo.z = ro.z + (v.z - mean) * r * go.z + bo.z;
    xo.w = ro.w + (v.w - mean) * r * go.w + bo.w;
    *(float4*)&x[base] = xo;
}

// ---------------------------------------------------------------------------
extern "C" void kernel_launch(void* const* d_in, const int* in_sizes, int n_in,
                              void* d_out, int out_size) {
    const float* nodes     = (const float*)d_in[0];
    const float* mha_in_w  = (const float*)d_in[14];
    const float* mha_in_b  = (const float*)d_in[15];
    const float* mha_out_w = (const float*)d_in[16];
    const float* mha_out_b = (const float*)d_in[17];
    const float* mha_ln_g  = (const float*)d_in[18];
    const float* mha_ln_b  = (const float*)d_in[19];
    float* x = (float*)d_out;

    float *o, *part;
    uint32_t* qkvp;
    cudaGetSymbolAddress((void**)&o,    g_o);
    cudaGetSymbolAddress((void**)&part, g_part);
    cudaGetSymbolAddress((void**)&qkvp, g_qkvp);

    static bool attr_done = false;
    if (!attr_done) {
        cudaFuncSetAttribute(attn_fused_kernel,
                             cudaFuncAttributeMaxDynamicSharedMemorySize,
                             ATTN_SMEM_BYTES);
        attr_done = true;
    }

    for (int l = 0; l < 2; l++) {
        const float* Wi = mha_in_w  + (size_t)l * H3n * Hn;
        const float* bi = mha_in_b  + (size_t)l * H3n;
        const float* Wo = mha_out_w + (size_t)l * Hn * Hn;
        const float* bo = mha_out_b + (size_t)l * Hn;
        const float* lg = mha_ln_g  + (size_t)l * Hn;
        const float* lb = mha_ln_b  + (size_t)l * Hn;

        const float* xin  = (l == 0) ? nodes : x;
        const float* resv = (l == 0) ? nodes : x;

        // qkv partials (sk=2, BN=64): grid 48x3x2 = 288 blocks (unchanged)
        gemm_tf32_splitk<64><<<dim3(H3n / 64, Tn / 64, SK_QKV), 256>>>(
            xin, Wi, part, Tn, H3n, Hn, Hn / SK_QKV);
        // pack: reduce partials + bias + tf32 convert, once
        qkv_pack<SK_QKV><<<(Tn * H3n / 4) / 256, 256>>>(part, bi, qkvp);
        // attention (pure-copy staging from packed buffer)
        attn_fused_kernel<<<dim3(Tn / 32, NHn), 256, ATTN_SMEM_BYTES>>>(qkvp, o);
        // out-proj partials (sk=4, BN=32): grid 32x3x4 = 384 blocks
        gemm_tf32_splitk<32><<<dim3(Hn / 32, Tn / 64, SK_OUT), 256>>>(
            o, Wo, part, Tn, Hn, Hn, Hn / SK_OUT);
        // fused reduce + bias + LN + residual (block-per-row)
        ln_residual_fused<SK_OUT><<<Tn, 256>>>(part, bo, lg, lb, resv, x);
    }
}